// round 16
// baseline (speedup 1.0000x reference)
#include <cuda_runtime.h>
#include <cuda_bf16.h>
#include <cuda_fp16.h>
#include <cstdint>

// Problem dims
#define ROWS   8192
#define FEAT   2048
#define HID    1024
#define GI_N   3072
#define NSEQ   128
#define NSTEP  64
#define NCLS   21

// ---------------- scratch ----------------
__device__ float g_gi[ROWS * GI_N];                 // time-major: row = t*128 + n
__device__ float g_hall[(NSTEP + 1) * NSEQ * HID];
__device__ __half g_fh[ROWS * FEAT], g_fl[ROWS * FEAT];
__device__ __half g_xh[ROWS * FEAT], g_xl[ROWS * FEAT];
__device__ __half g_wfh[FEAT * FEAT], g_wfl[FEAT * FEAT];
__device__ __half g_wih[GI_N * FEAT], g_wil[GI_N * FEAT];
__device__ __nv_bfloat16 g_whp[GI_N * HID], g_wlp[GI_N * HID];
__device__ __nv_bfloat16 g_hbh[2 * NSEQ * HID], g_hbl[2 * NSEQ * HID];
__device__ unsigned int g_bar;

__device__ __forceinline__ float sigmoidf_(float x) { return 1.0f / (1.0f + expf(-x)); }

__device__ __forceinline__ uint32_t smem_u32(const void* p) {
    uint32_t a;
    asm("{ .reg .u64 t; cvta.to.shared.u64 t, %1; cvt.u32.u64 %0, t; }" : "=r"(a) : "l"(p));
    return a;
}
__device__ __forceinline__ void cp_async16(uint32_t dst, const void* src) {
    asm volatile("cp.async.cg.shared.global [%0], [%1], 16;" :: "r"(dst), "l"(src) : "memory");
}
__device__ __forceinline__ void ldmx4(uint32_t* r, uint32_t addr) {
    asm volatile("ldmatrix.sync.aligned.m8n8.x4.shared.b16 {%0,%1,%2,%3}, [%4];"
                 : "=r"(r[0]), "=r"(r[1]), "=r"(r[2]), "=r"(r[3]) : "r"(addr));
}
__device__ __forceinline__ void mma16816(float* c, const uint32_t* a, uint32_t b0, uint32_t b1) {
    asm volatile(
        "mma.sync.aligned.m16n8k16.row.col.f32.bf16.bf16.f32 "
        "{%0,%1,%2,%3}, {%4,%5,%6,%7}, {%8,%9}, {%0,%1,%2,%3};"
        : "+f"(c[0]), "+f"(c[1]), "+f"(c[2]), "+f"(c[3])
        : "r"(a[0]), "r"(a[1]), "r"(a[2]), "r"(a[3]), "r"(b0), "r"(b1));
}
__device__ __forceinline__ void mma16816h(float* c, const uint32_t* a, uint32_t b0, uint32_t b1) {
    asm volatile(
        "mma.sync.aligned.m16n8k16.row.col.f32.f16.f16.f32 "
        "{%0,%1,%2,%3}, {%4,%5,%6,%7}, {%8,%9}, {%0,%1,%2,%3};"
        : "+f"(c[0]), "+f"(c[1]), "+f"(c[2]), "+f"(c[3])
        : "r"(a[0]), "r"(a[1]), "r"(a[2]), "r"(a[3]), "r"(b0), "r"(b1));
}

// ---------------- threefry2x32 fold, key (0,42) ----------------
__device__ __forceinline__ unsigned int threefry_fold(unsigned int c1)
{
    const unsigned int ks1 = 42u;
    const unsigned int ks2 = 42u ^ 0x1BD11BDAu;
    unsigned int x0 = 0u;
    unsigned int x1 = c1 + ks1;
#define TFR(r) { x0 += x1; x1 = (x1 << (r)) | (x1 >> (32 - (r))); x1 ^= x0; }
    TFR(13) TFR(15) TFR(26) TFR(6)
    x0 += ks1; x1 += ks2 + 1u;
    TFR(17) TFR(29) TFR(16) TFR(24)
    x0 += ks2; x1 += 0u + 2u;
    TFR(13) TFR(15) TFR(26) TFR(6)
    x0 += 0u; x1 += ks1 + 3u;
    TFR(17) TFR(29) TFR(16) TFR(24)
    x0 += ks1; x1 += ks2 + 4u;
    TFR(13) TFR(15) TFR(26) TFR(6)
    x0 += ks2; x1 += 0u + 5u;
#undef TFR
    return x0 ^ x1;
}

// ---------------- fp32 -> fp16 hi/lo ----------------
__global__ __launch_bounds__(256) void convert_hilo_h(
    const float* __restrict__ in, __half* __restrict__ hi,
    __half* __restrict__ lo, int n)
{
    int i = (blockIdx.x * 256 + threadIdx.x) * 4;
    if (i >= n) return;
    float4 v = *(const float4*)(in + i);
    float vv[4] = {v.x, v.y, v.z, v.w};
    __half h[4], l[4];
#pragma unroll
    for (int e = 0; e < 4; e++) {
        h[e] = __float2half_rn(vv[e]);
        l[e] = __float2half_rn(vv[e] - __half2float(h[e]));
    }
    *(__half2*)(hi + i)     = __half2(h[0], h[1]);
    *(__half2*)(hi + i + 2) = __half2(h[2], h[3]);
    *(__half2*)(lo + i)     = __half2(l[0], l[1]);
    *(__half2*)(lo + i + 2) = __half2(l[2], l[3]);
}

// ---- w_hh convert + gate-interleave permute (bf16, scan) ----
__global__ __launch_bounds__(256) void convert_whh_perm(
    const float* __restrict__ in, __nv_bfloat16* __restrict__ hi,
    __nv_bfloat16* __restrict__ lo)
{
    int i = (blockIdx.x * 256 + threadIdx.x) * 4;
    int r = i >> 10;
    int col = i & 1023;
    int gate = r >> 10, rem = r & 1023;
    int blk = rem >> 4, u = rem & 15;
    int rp = blk * 48 + gate * 16 + u;
    size_t o = (size_t)rp * HID + col;

    float4 v = *(const float4*)(in + i);
    float vv[4] = {v.x, v.y, v.z, v.w};
    __nv_bfloat16 h[4], l[4];
#pragma unroll
    for (int e = 0; e < 4; e++) {
        h[e] = __float2bfloat16_rn(vv[e]);
        l[e] = __float2bfloat16_rn(vv[e] - __bfloat162float(h[e]));
    }
    *(__nv_bfloat162*)(hi + o)     = __nv_bfloat162(h[0], h[1]);
    *(__nv_bfloat162*)(hi + o + 2) = __nv_bfloat162(h[2], h[3]);
    *(__nv_bfloat162*)(lo + o)     = __nv_bfloat162(l[0], l[1]);
    *(__nv_bfloat162*)(lo + o + 2) = __nv_bfloat162(l[2], l[3]);
}

// ====== big mma.sync fp16 2-pass GEMM (validated R15) ========================================
#define LDAB  144
#define BUFB  (128 * LDAB)
#define STAGEB (3 * BUFB)          // 55296: Ah, Al, Wh
#define MM_SMEM (3 * STAGEB)       // 165888

template<int MODE>
__global__ __launch_bounds__(256) void mma_gemm(
    const __half* __restrict__ Ah, const __half* __restrict__ Al,
    const __half* __restrict__ Wh,
    const float* __restrict__ bias, float* __restrict__ Cf,
    __half* __restrict__ Ch, __half* __restrict__ Cl,
    int K, int Nout)
{
    extern __shared__ char smem[];
    const uint32_t sb = smem_u32(smem);
    const int tid = threadIdx.x;
    const int wid = tid >> 5, lane = tid & 31;
    const int wm = wid & 3, wn = wid >> 2;
    const int g = lane >> 2, t = lane & 3;
    const int m0 = blockIdx.y * 128, n0 = blockIdx.x * 128;
    const size_t rowb = (size_t)K * 2;
    const char* srcp[3] = { (const char*)Ah + (size_t)m0 * rowb,
                            (const char*)Al + (size_t)m0 * rowb,
                            (const char*)Wh + (size_t)n0 * rowb };
    const int nstages = K / 64;

    float c[2][8][4];
#pragma unroll
    for (int i = 0; i < 2; i++)
#pragma unroll
        for (int j = 0; j < 8; j++)
#pragma unroll
            for (int q = 0; q < 4; q++) c[i][j][q] = 0.0f;

    auto load_stage = [&](int s) {
        uint32_t dstb = sb + (uint32_t)(s % 3) * STAGEB;
        int kb = s * 128;
#pragma unroll
        for (int it = 0; it < 12; it++) {
            int id = tid + it * 256;
            int buf = id >> 10;
            int local = id & 1023;
            int row = local >> 3, cc = local & 7;
            cp_async16(dstb + buf * BUFB + row * LDAB + cc * 16,
                       srcp[buf] + (size_t)row * rowb + kb + cc * 16);
        }
        asm volatile("cp.async.commit_group;" ::: "memory");
    };

    load_stage(0);
    if (nstages > 1) load_stage(1);
    for (int s = 0; s < nstages; s++) {
        if (s + 2 < nstages) load_stage(s + 2);
        const int rem = nstages - s;
        if (rem >= 3)      asm volatile("cp.async.wait_group 2;" ::: "memory");
        else if (rem == 2) asm volatile("cp.async.wait_group 1;" ::: "memory");
        else               asm volatile("cp.async.wait_group 0;" ::: "memory");
        __syncthreads();

        const uint32_t base = sb + (uint32_t)(s % 3) * STAGEB;
        const uint32_t aoff = base + (wm * 32 + (lane & 15)) * LDAB + (lane >> 4) * 16;
        const uint32_t woff = base + 2 * BUFB + (wn * 64 + (lane & 15)) * LDAB + (lane >> 4) * 16;

#pragma unroll
        for (int ks = 0; ks < 4; ks++) {
            const uint32_t kb2 = ks * 32;
            uint32_t ah[2][4], al[2][4], wh[4][4];
            ldmx4(ah[0], aoff + kb2);
            ldmx4(ah[1], aoff + 16 * LDAB + kb2);
            ldmx4(al[0], aoff + BUFB + kb2);
            ldmx4(al[1], aoff + BUFB + 16 * LDAB + kb2);
#pragma unroll
            for (int p = 0; p < 4; p++)
                ldmx4(wh[p], woff + p * 16 * LDAB + kb2);
#pragma unroll
            for (int mt = 0; mt < 2; mt++)
#pragma unroll
                for (int nt = 0; nt < 8; nt++) {
                    uint32_t b0h = wh[nt >> 1][nt & 1], b1h = wh[nt >> 1][2 + (nt & 1)];
                    mma16816h(c[mt][nt], ah[mt], b0h, b1h);
                    mma16816h(c[mt][nt], al[mt], b0h, b1h);
                }
        }
        __syncthreads();
    }

#pragma unroll
    for (int mt = 0; mt < 2; mt++)
#pragma unroll
        for (int nt = 0; nt < 8; nt++) {
            const int mrow = m0 + wm * 32 + mt * 16 + g;
            const int ncol = n0 + wn * 64 + nt * 8 + t * 2;
            const float b0 = bias[ncol], b1 = bias[ncol + 1];
#pragma unroll
            for (int half = 0; half < 2; half++) {
                const int m = mrow + half * 8;
                float v0 = c[mt][nt][half * 2 + 0] + b0;
                float v1 = c[mt][nt][half * 2 + 1] + b1;
                if (MODE == 0) {
                    v0 = fmaxf(v0, 0.0f); v1 = fmaxf(v1, 0.0f);
                    unsigned int i0 = (unsigned int)(m * 2048 + ncol);
                    unsigned int bt0 = threefry_fold(i0);
                    unsigned int bt1 = threefry_fold(i0 + 1);
                    float u0 = __uint_as_float((bt0 >> 9) | 0x3f800000u) - 1.0f;
                    float u1 = __uint_as_float((bt1 >> 9) | 0x3f800000u) - 1.0f;
                    v0 = (u0 < 0.7f) ? v0 * (1.0f / 0.7f) : 0.0f;
                    v1 = (u1 < 0.7f) ? v1 * (1.0f / 0.7f) : 0.0f;
                    *(float2*)(Cf + (size_t)m * 2048 + ncol) = make_float2(v0, v1);
                    __half h0 = __float2half_rn(v0);
                    __half h1 = __float2half_rn(v1);
                    *(__half2*)(Ch + (size_t)m * 2048 + ncol) = __half2(h0, h1);
                    *(__half2*)(Cl + (size_t)m * 2048 + ncol) = __half2(
                        __float2half_rn(v0 - __half2float(h0)),
                        __float2half_rn(v1 - __half2float(h1)));
                } else {
                    int rp = (m & 63) * 128 + (m >> 6);
                    *(float2*)(Cf + (size_t)rp * Nout + ncol) = make_float2(v0, v1);
                }
            }
        }
}

// =================== persistent GRU scan — 256 threads, intra-chunk K-split ==================
#define PW_PITCH 2064
#define PS_WH 0
#define PS_WL (48 * PW_PITCH)                  // 99072
#define PS_AH (2 * 48 * PW_PITCH)              // 198144
#define PABUF (64 * LDAB)                      // 9216
#define PS_AL (PS_AH + PABUF)                  // 207360
#define PS_TOTAL (PS_AL + PABUF)               // 216576

__global__ __launch_bounds__(256) void gru_persist(
    const __nv_bfloat16* __restrict__ Wp, const __nv_bfloat16* __restrict__ Lp,
    const float* __restrict__ gi, const float* __restrict__ bhh,
    __nv_bfloat16* __restrict__ hbh, __nv_bfloat16* __restrict__ hbl)
{
    extern __shared__ char smem[];
    const uint32_t sb = smem_u32(smem);
    const int tid = threadIdx.x;
    const int wg = tid >> 7;             // K-split group 0/1
    const int wm = (tid >> 5) & 3, lane = tid & 31;
    const int nb = blockIdx.x;
    const int m0 = blockIdx.y * 64;
    const int np0 = nb * 48;

    // ---- preload resident W hi/lo (once): 12288 x 16B, 48/thread ----
    for (int it = 0; it < 48; it++) {
        int id = tid + it * 256;
        int buf = id >= 6144;
        int local = buf ? id - 6144 : id;
        int row = local >> 7, c = local & 127;
        const char* src = (const char*)(buf ? Lp : Wp) + (size_t)(np0 + row) * 2048 + c * 16;
        cp_async16(sb + (buf ? PS_WL : PS_WH) + row * PW_PITCH + c * 16, src);
    }
    asm volatile("cp.async.commit_group;" ::: "memory");
    asm volatile("cp.async.wait_group 0;" ::: "memory");
    __syncthreads();

    for (int t = 0; t < NSTEP; t++) {
        const __nv_bfloat16* Hh = hbh + (size_t)(t & 1) * NSEQ * HID;
        const __nv_bfloat16* Hl = hbl + (size_t)(t & 1) * NSEQ * HID;

        float c[6][4];
#pragma unroll
        for (int j = 0; j < 6; j++)
#pragma unroll
            for (int q = 0; q < 4; q++) c[j][q] = 0.0f;

        // chunk staging: 1024 x 16B, 4/thread
        uint4 rg[4];
#pragma unroll
        for (int it = 0; it < 4; it++) {
            int id = tid + it * 256;
            int buf = id >> 9, local = id & 511;
            int row = local >> 3, cc = local & 7;
            const char* src = (const char*)(buf ? Hl : Hh)
                              + (size_t)(m0 + row) * 2048 + cc * 16;
            rg[it] = *(const uint4*)src;
        }

#pragma unroll 1
        for (int ch = 0; ch < 16; ch++) {
#pragma unroll
            for (int it = 0; it < 4; it++) {
                int id = tid + it * 256;
                int buf = id >> 9, local = id & 511;
                int row = local >> 3, cc = local & 7;
                *(uint4*)(smem + (buf ? PS_AL : PS_AH) + row * LDAB + cc * 16) = rg[it];
            }
            __syncthreads();
            if (ch < 15) {
#pragma unroll
                for (int it = 0; it < 4; it++) {
                    int id = tid + it * 256;
                    int buf = id >> 9, local = id & 511;
                    int row = local >> 3, cc = local & 7;
                    const char* src = (const char*)(buf ? Hl : Hh)
                                      + (size_t)(m0 + row) * 2048 + (ch + 1) * 128 + cc * 16;
                    rg[it] = *(const uint4*)src;
                }
            }
            const uint32_t aoff  = sb + PS_AH + (wm * 16 + (lane & 15)) * LDAB + (lane >> 4) * 16;
            const uint32_t aoffL = sb + PS_AL + (wm * 16 + (lane & 15)) * LDAB + (lane >> 4) * 16;
            const uint32_t whoff = sb + PS_WH + (lane & 15) * PW_PITCH + (lane >> 4) * 16;
            const uint32_t wloff = sb + PS_WL + (lane & 15) * PW_PITCH + (lane >> 4) * 16;
            // K-split: group wg handles ks = wg*2 + {0,1}
#pragma unroll
            for (int ks2 = 0; ks2 < 2; ks2++) {
                const int ks = wg * 2 + ks2;
                const uint32_t kbA = ks * 32;
                const uint32_t kbW = (ch * 4 + ks) * 32;
                uint32_t ah[4], al[4], wh[3][4], wl[3][4];
                ldmx4(ah, aoff + kbA);
                ldmx4(al, aoffL + kbA);
#pragma unroll
                for (int p = 0; p < 3; p++) {
                    ldmx4(wh[p], whoff + p * 16 * PW_PITCH + kbW);
                    ldmx4(wl[p], wloff + p * 16 * PW_PITCH + kbW);
                }
#pragma unroll
                for (int p = 0; p < 3; p++)
#pragma unroll
                    for (int half = 0; half < 2; half++) {
                        float* cc = c[p * 2 + half];
                        mma16816(cc, ah, wh[p][half], wh[p][2 + half]);
                        mma16816(cc, ah, wl[p][half], wl[p][2 + half]);
                        mma16816(cc, al, wh[p][half], wh[p][2 + half]);
                    }
            }
            __syncthreads();
        }

        // ---- cross-group reduction: group 1 spills 24 floats, group 0 adds ----
        if (wg == 1) {
            float4* dst = (float4*)(smem + PS_AH + (tid & 127) * 96);
#pragma unroll
            for (int j = 0; j < 6; j++)
                dst[j] = make_float4(c[j][0], c[j][1], c[j][2], c[j][3]);
        }
        __syncthreads();
        if (wg == 0) {
            const float4* src = (const float4*)(smem + PS_AH + tid * 96);
#pragma unroll
            for (int j = 0; j < 6; j++) {
                float4 v = src[j];
                c[j][0] += v.x; c[j][1] += v.y; c[j][2] += v.z; c[j][3] += v.w;
            }

            // ---- fused gate epilogue (group 0 only; mapping validated R9/R11) ----
            const float* hprev = g_hall + (size_t)t * NSEQ * HID;
            float* hout        = g_hall + (size_t)(t + 1) * NSEQ * HID;
            __nv_bfloat16* Oh = hbh + (size_t)((t + 1) & 1) * NSEQ * HID;
            __nv_bfloat16* Ol = hbl + (size_t)((t + 1) & 1) * NSEQ * HID;
#pragma unroll
            for (int half = 0; half < 2; half++) {
                const int unit0 = nb * 16 + half * 8 + (lane & 3) * 2;
                const float2 br2 = *(const float2*)(bhh + unit0);
                const float2 bz2 = *(const float2*)(bhh + HID + unit0);
                const float2 bn2 = *(const float2*)(bhh + 2 * HID + unit0);
#pragma unroll
                for (int mh = 0; mh < 2; mh++) {
                    const int n = m0 + wm * 16 + (lane >> 2) + mh * 8;
                    const size_t gib = (size_t)(t * 128 + n) * GI_N;
                    const float2 ir2 = *(const float2*)(gi + gib + unit0);
                    const float2 iz2 = *(const float2*)(gi + gib + HID + unit0);
                    const float2 in2 = *(const float2*)(gi + gib + 2 * HID + unit0);
                    const float2 hp2 = *(const float2*)(hprev + (size_t)n * HID + unit0);
                    float h2[2];
#pragma unroll
                    for (int e = 0; e < 2; e++) {
                        const int ci = mh * 2 + e;
                        float ir = e ? ir2.y : ir2.x, iz = e ? iz2.y : iz2.x, in_ = e ? in2.y : in2.x;
                        float br = e ? br2.y : br2.x, bz = e ? bz2.y : bz2.x, bn = e ? bn2.y : bn2.x;
                        float hp = e ? hp2.y : hp2.x;
                        float r  = sigmoidf_(ir + c[half][ci] + br);
                        float z  = sigmoidf_(iz + c[2 + half][ci] + bz);
                        float nn = tanhf(in_ + r * (c[4 + half][ci] + bn));
                        h2[e] = (1.0f - z) * nn + z * hp;
                    }
                    *(float2*)(hout + (size_t)n * HID + unit0) = make_float2(h2[0], h2[1]);
                    __nv_bfloat16 b0 = __float2bfloat16_rn(h2[0]);
                    __nv_bfloat16 b1 = __float2bfloat16_rn(h2[1]);
                    *(__nv_bfloat162*)(Oh + (size_t)n * HID + unit0) = __nv_bfloat162(b0, b1);
                    *(__nv_bfloat162*)(Ol + (size_t)n * HID + unit0) = __nv_bfloat162(
                        __float2bfloat16_rn(h2[0] - __bfloat162float(b0)),
                        __float2bfloat16_rn(h2[1] - __bfloat162float(b1)));
                }
            }
        }

        // ---- grid barrier ----
        __syncthreads();
        if (tid == 0) {
            __threadfence();
            atomicAdd(&g_bar, 1u);
            const unsigned int target = 128u * (unsigned int)(t + 1);
            while (*(volatile unsigned int*)&g_bar < target) __nanosleep(64);
        }
        __syncthreads();
    }
}

// ======================= vl & cf small-N GEMMs (unchanged, validated) =========================
__global__ __launch_bounds__(256) void vl_kernel(
    const float* __restrict__ A, const float* __restrict__ W,
    const float* __restrict__ bias, float* __restrict__ out)
{
    __shared__ float As[32][65];
    __shared__ float Ws[24][65];
    const int tid = threadIdx.x;
    const int r = tid >> 3, s = tid & 7;
    const int r0 = blockIdx.x * 32;
    float acc[3] = {0.f, 0.f, 0.f};

    for (int kc = 0; kc < FEAT; kc += 64) {
#pragma unroll
        for (int jj = 0; jj < 2; jj++) {
            int id = tid + jj * 256;
            int row = id >> 4, q = id & 15;
            float4 v = *(const float4*)(A + (size_t)(r0 + row) * FEAT + kc + q * 4);
            As[row][q*4+0] = v.x; As[row][q*4+1] = v.y;
            As[row][q*4+2] = v.z; As[row][q*4+3] = v.w;
        }
#pragma unroll
        for (int jj = 0; jj < 2; jj++) {
            int id = tid + jj * 256;
            if (id < 21 * 16) {
                int row = id >> 4, q = id & 15;
                float4 v = *(const float4*)(W + (size_t)row * FEAT + kc + q * 4);
                Ws[row][q*4+0] = v.x; Ws[row][q*4+1] = v.y;
                Ws[row][q*4+2] = v.z; Ws[row][q*4+3] = v.w;
            }
        }
        __syncthreads();
#pragma unroll
        for (int kk = 0; kk < 64; kk++) {
            float a = As[r][kk];
#pragma unroll
            for (int cc = 0; cc < 3; cc++) {
                int c = s + 8 * cc;
                if (c < NCLS) acc[cc] += a * Ws[c][kk];
            }
        }
        __syncthreads();
    }
    int row = r0 + r;
#pragma unroll
    for (int cc = 0; cc < 3; cc++) {
        int c = s + 8 * cc;
        if (c < NCLS) out[(size_t)row * NCLS + c] = acc[cc] + bias[c];
    }
}

__global__ __launch_bounds__(256) void cf_kernel(
    const float* __restrict__ Hrows,
    const float* __restrict__ cfw, const float* __restrict__ cfb,
    const float* __restrict__ mkw, const float* __restrict__ mkb,
    float* __restrict__ enc, float* __restrict__ mask)
{
    __shared__ float As[32][65];
    __shared__ float Ws[24][65];
    const int tid = threadIdx.x;
    const int r = tid >> 3, s = tid & 7;
    const int r0 = blockIdx.x * 32;
    float acc[3] = {0.f, 0.f, 0.f};

    for (int kc = 0; kc < HID; kc += 64) {
#pragma unroll
        for (int jj = 0; jj < 2; jj++) {
            int id = tid + jj * 256;
            int row = id >> 4, q = id & 15;
            float4 v = *(const float4*)(Hrows + (size_t)(r0 + row) * HID + kc + q * 4);
            As[row][q*4+0] = fmaxf(v.x, 0.0f); As[row][q*4+1] = fmaxf(v.y, 0.0f);
            As[row][q*4+2] = fmaxf(v.z, 0.0f); As[row][q*4+3] = fmaxf(v.w, 0.0f);
        }
#pragma unroll
        for (int jj = 0; jj < 2; jj++) {
            int id = tid + jj * 256;
            if (id < 24 * 16) {
                int row = id >> 4, q = id & 15;
                const float* src = (row < 22) ? (cfw + (size_t)row * HID)
                                              : (mkw + (size_t)(row - 22) * HID);
                float4 v = *(const float4*)(src + kc + q * 4);
                Ws[row][q*4+0] = v.x; Ws[row][q*4+1] = v.y;
                Ws[row][q*4+2] = v.z; Ws[row][q*4+3] = v.w;
            }
        }
        __syncthreads();
#pragma unroll
        for (int kk = 0; kk < 64; kk++) {
            float a = As[r][kk];
#pragma unroll
            for (int cc = 0; cc < 3; cc++) {
                int c = s + 8 * cc;
                acc[cc] += a * Ws[c][kk];
            }
        }
        __syncthreads();
    }
    int row = r0 + r;
#pragma unroll
    for (int cc = 0; cc < 3; cc++) {
        int c = s + 8 * cc;
        float b = (c < 22) ? cfb[c] : mkb[c - 22];
        float val = acc[cc] + b;
        if (c < 22) enc[(size_t)row * 22 + c] = val;
        else        mask[(size_t)row * 2 + (c - 22)] = val;
    }
}

// ======================= launch (sequential topology) =========================================
extern "C" void kernel_launch(void* const* d_in, const int* in_sizes, int n_in,
                              void* d_out, int out_size)
{
    const float* feats = (const float*)d_in[0];
    const float* fc_w  = (const float*)d_in[1];
    const float* fc_b  = (const float*)d_in[2];
    const float* cls_w = (const float*)d_in[3];
    const float* cls_b = (const float*)d_in[4];
    const float* w_ih  = (const float*)d_in[5];
    const float* w_hh  = (const float*)d_in[6];
    const float* b_ih  = (const float*)d_in[7];
    const float* b_hh  = (const float*)d_in[8];
    const float* cf_w  = (const float*)d_in[9];
    const float* cf_b  = (const float*)d_in[10];
    const float* mk_w  = (const float*)d_in[11];
    const float* mk_b  = (const float*)d_in[12];

    float* out  = (float*)d_out;
    float* enc  = out;
    float* mask = out + 8192 * 22;
    float* xbuf = out + 8192 * 22 + 8192 * 2;
    float* vl   = xbuf + (size_t)ROWS * FEAT;

    float *gi_ptr, *hall_ptr;
    __half *fh, *fl, *xh, *xl, *wfh, *wfl, *wihh, *wihl;
    __nv_bfloat16 *whp, *wlp, *hbh, *hbl;
    unsigned int* bar_ptr;
    cudaGetSymbolAddress((void**)&gi_ptr, g_gi);
    cudaGetSymbolAddress((void**)&hall_ptr, g_hall);
    cudaGetSymbolAddress((void**)&fh, g_fh);   cudaGetSymbolAddress((void**)&fl, g_fl);
    cudaGetSymbolAddress((void**)&xh, g_xh);   cudaGetSymbolAddress((void**)&xl, g_xl);
    cudaGetSymbolAddress((void**)&wfh, g_wfh); cudaGetSymbolAddress((void**)&wfl, g_wfl);
    cudaGetSymbolAddress((void**)&wihh, g_wih); cudaGetSymbolAddress((void**)&wihl, g_wil);
    cudaGetSymbolAddress((void**)&whp, g_whp); cudaGetSymbolAddress((void**)&wlp, g_wlp);
    cudaGetSymbolAddress((void**)&hbh, g_hbh); cudaGetSymbolAddress((void**)&hbl, g_hbl);
    cudaGetSymbolAddress((void**)&bar_ptr, g_bar);

    cudaFuncSetAttribute(mma_gemm<0>, cudaFuncAttributeMaxDynamicSharedMemorySize, MM_SMEM);
    cudaFuncSetAttribute(mma_gemm<1>, cudaFuncAttributeMaxDynamicSharedMemorySize, MM_SMEM);
    cudaFuncSetAttribute(gru_persist, cudaFuncAttributeMaxDynamicSharedMemorySize, PS_TOTAL);

    // 0. converts + resets
    convert_hilo_h<<<(ROWS * FEAT) / 1024, 256>>>(feats, fh, fl, ROWS * FEAT);
    convert_hilo_h<<<(FEAT * FEAT) / 1024, 256>>>(fc_w, wfh, wfl, FEAT * FEAT);
    convert_hilo_h<<<(GI_N * FEAT) / 1024, 256>>>(w_ih, wihh, wihl, GI_N * FEAT);
    convert_whh_perm<<<(GI_N * HID) / 1024, 256>>>(w_hh, whp, wlp);
    cudaMemsetAsync(bar_ptr, 0, sizeof(unsigned int));
    cudaMemsetAsync(hall_ptr, 0, (size_t)NSEQ * HID * sizeof(float));
    cudaMemsetAsync(hbh, 0, (size_t)NSEQ * HID * sizeof(__nv_bfloat16));
    cudaMemsetAsync(hbl, 0, (size_t)NSEQ * HID * sizeof(__nv_bfloat16));

    // 1. fc GEMM (fp16 2-pass) + fused epilogue
    mma_gemm<0><<<dim3(FEAT / 128, ROWS / 128), 256, MM_SMEM>>>(
        fh, fl, wfh, fc_b, xbuf, xh, xl, FEAT, FEAT);

    // 2. vl_preds
    vl_kernel<<<ROWS / 32, 256>>>(xbuf, cls_w, cls_b, vl);

    // 3. gi (fp16 2-pass, time-major)
    mma_gemm<1><<<dim3(GI_N / 128, ROWS / 128), 256, MM_SMEM>>>(
        xh, xl, wihh, b_ih, gi_ptr, nullptr, nullptr, FEAT, GI_N);

    // 4. persistent GRU scan (256 threads, K-split)
    gru_persist<<<dim3(64, 2), 256, PS_TOTAL>>>(whp, wlp, gi_ptr, b_hh, hbh, hbl);

    // 5. enc/mask scores
    cf_kernel<<<ROWS / 32, 256>>>(hall_ptr + (size_t)NSEQ * HID,
                                  cf_w, cf_b, mk_w, mk_b, enc, mask);
}

// round 17
// speedup vs baseline: 1.1894x; 1.1894x over previous
#include <cuda_runtime.h>
#include <cuda_bf16.h>
#include <cuda_fp16.h>
#include <cstdint>

// Problem dims
#define ROWS   8192
#define FEAT   2048
#define HID    1024
#define GI_N   3072
#define NSEQ   128
#define NSTEP  64
#define NCLS   21

// ---------------- scratch ----------------
__device__ float g_gi[ROWS * GI_N];                 // time-major: row = t*128 + n
__device__ float g_hall[(NSTEP + 1) * NSEQ * HID];
__device__ __half g_fh[ROWS * FEAT], g_fl[ROWS * FEAT];
__device__ __half g_xh[ROWS * FEAT], g_xl[ROWS * FEAT];
__device__ __half g_wfh[FEAT * FEAT], g_wfl[FEAT * FEAT];
__device__ __half g_wih[GI_N * FEAT], g_wil[GI_N * FEAT];
__device__ __half g_whp[GI_N * HID];                             // w_hh permuted fp16 (hi only)
__device__ __half g_hbh[2 * NSEQ * HID], g_hbl[2 * NSEQ * HID];  // h ping-pong fp16 hi/lo
__device__ unsigned int g_bar;

__device__ __forceinline__ float sigmoidf_(float x) { return 1.0f / (1.0f + expf(-x)); }

__device__ __forceinline__ uint32_t smem_u32(const void* p) {
    uint32_t a;
    asm("{ .reg .u64 t; cvta.to.shared.u64 t, %1; cvt.u32.u64 %0, t; }" : "=r"(a) : "l"(p));
    return a;
}
__device__ __forceinline__ void cp_async16(uint32_t dst, const void* src) {
    asm volatile("cp.async.cg.shared.global [%0], [%1], 16;" :: "r"(dst), "l"(src) : "memory");
}
__device__ __forceinline__ void ldmx4(uint32_t* r, uint32_t addr) {
    asm volatile("ldmatrix.sync.aligned.m8n8.x4.shared.b16 {%0,%1,%2,%3}, [%4];"
                 : "=r"(r[0]), "=r"(r[1]), "=r"(r[2]), "=r"(r[3]) : "r"(addr));
}
__device__ __forceinline__ void mma16816h(float* c, const uint32_t* a, uint32_t b0, uint32_t b1) {
    asm volatile(
        "mma.sync.aligned.m16n8k16.row.col.f32.f16.f16.f32 "
        "{%0,%1,%2,%3}, {%4,%5,%6,%7}, {%8,%9}, {%0,%1,%2,%3};"
        : "+f"(c[0]), "+f"(c[1]), "+f"(c[2]), "+f"(c[3])
        : "r"(a[0]), "r"(a[1]), "r"(a[2]), "r"(a[3]), "r"(b0), "r"(b1));
}

// ---------------- threefry2x32 fold, key (0,42) ----------------
__device__ __forceinline__ unsigned int threefry_fold(unsigned int c1)
{
    const unsigned int ks1 = 42u;
    const unsigned int ks2 = 42u ^ 0x1BD11BDAu;
    unsigned int x0 = 0u;
    unsigned int x1 = c1 + ks1;
#define TFR(r) { x0 += x1; x1 = (x1 << (r)) | (x1 >> (32 - (r))); x1 ^= x0; }
    TFR(13) TFR(15) TFR(26) TFR(6)
    x0 += ks1; x1 += ks2 + 1u;
    TFR(17) TFR(29) TFR(16) TFR(24)
    x0 += ks2; x1 += 0u + 2u;
    TFR(13) TFR(15) TFR(26) TFR(6)
    x0 += 0u; x1 += ks1 + 3u;
    TFR(17) TFR(29) TFR(16) TFR(24)
    x0 += ks1; x1 += ks2 + 4u;
    TFR(13) TFR(15) TFR(26) TFR(6)
    x0 += ks2; x1 += 0u + 5u;
#undef TFR
    return x0 ^ x1;
}

// ---------------- fp32 -> fp16 hi/lo ----------------
__global__ __launch_bounds__(256) void convert_hilo_h(
    const float* __restrict__ in, __half* __restrict__ hi,
    __half* __restrict__ lo, int n)
{
    int i = (blockIdx.x * 256 + threadIdx.x) * 4;
    if (i >= n) return;
    float4 v = *(const float4*)(in + i);
    float vv[4] = {v.x, v.y, v.z, v.w};
    __half h[4], l[4];
#pragma unroll
    for (int e = 0; e < 4; e++) {
        h[e] = __float2half_rn(vv[e]);
        l[e] = __float2half_rn(vv[e] - __half2float(h[e]));
    }
    *(__half2*)(hi + i)     = __half2(h[0], h[1]);
    *(__half2*)(hi + i + 2) = __half2(h[2], h[3]);
    *(__half2*)(lo + i)     = __half2(l[0], l[1]);
    *(__half2*)(lo + i + 2) = __half2(l[2], l[3]);
}

// ---- w_hh convert (fp16 hi only) + gate-interleave permute ----
__global__ __launch_bounds__(256) void convert_whh_perm(
    const float* __restrict__ in, __half* __restrict__ hi)
{
    int i = (blockIdx.x * 256 + threadIdx.x) * 4;
    int r = i >> 10;
    int col = i & 1023;
    int gate = r >> 10, rem = r & 1023;
    int blk = rem >> 4, u = rem & 15;
    int rp = blk * 48 + gate * 16 + u;
    size_t o = (size_t)rp * HID + col;

    float4 v = *(const float4*)(in + i);
    *(__half2*)(hi + o)     = __half2(__float2half_rn(v.x), __float2half_rn(v.y));
    *(__half2*)(hi + o + 2) = __half2(__float2half_rn(v.z), __float2half_rn(v.w));
}

// ====== big mma.sync fp16 2-pass GEMM (validated R15, unchanged) =============================
#define LDAB  144
#define BUFB  (128 * LDAB)
#define STAGEB (3 * BUFB)
#define MM_SMEM (3 * STAGEB)

template<int MODE>
__global__ __launch_bounds__(256) void mma_gemm(
    const __half* __restrict__ Ah, const __half* __restrict__ Al,
    const __half* __restrict__ Wh,
    const float* __restrict__ bias, float* __restrict__ Cf,
    __half* __restrict__ Ch, __half* __restrict__ Cl,
    int K, int Nout)
{
    extern __shared__ char smem[];
    const uint32_t sb = smem_u32(smem);
    const int tid = threadIdx.x;
    const int wid = tid >> 5, lane = tid & 31;
    const int wm = wid & 3, wn = wid >> 2;
    const int g = lane >> 2, t = lane & 3;
    const int m0 = blockIdx.y * 128, n0 = blockIdx.x * 128;
    const size_t rowb = (size_t)K * 2;
    const char* srcp[3] = { (const char*)Ah + (size_t)m0 * rowb,
                            (const char*)Al + (size_t)m0 * rowb,
                            (const char*)Wh + (size_t)n0 * rowb };
    const int nstages = K / 64;

    float c[2][8][4];
#pragma unroll
    for (int i = 0; i < 2; i++)
#pragma unroll
        for (int j = 0; j < 8; j++)
#pragma unroll
            for (int q = 0; q < 4; q++) c[i][j][q] = 0.0f;

    auto load_stage = [&](int s) {
        uint32_t dstb = sb + (uint32_t)(s % 3) * STAGEB;
        int kb = s * 128;
#pragma unroll
        for (int it = 0; it < 12; it++) {
            int id = tid + it * 256;
            int buf = id >> 10;
            int local = id & 1023;
            int row = local >> 3, cc = local & 7;
            cp_async16(dstb + buf * BUFB + row * LDAB + cc * 16,
                       srcp[buf] + (size_t)row * rowb + kb + cc * 16);
        }
        asm volatile("cp.async.commit_group;" ::: "memory");
    };

    load_stage(0);
    if (nstages > 1) load_stage(1);
    for (int s = 0; s < nstages; s++) {
        if (s + 2 < nstages) load_stage(s + 2);
        const int rem = nstages - s;
        if (rem >= 3)      asm volatile("cp.async.wait_group 2;" ::: "memory");
        else if (rem == 2) asm volatile("cp.async.wait_group 1;" ::: "memory");
        else               asm volatile("cp.async.wait_group 0;" ::: "memory");
        __syncthreads();

        const uint32_t base = sb + (uint32_t)(s % 3) * STAGEB;
        const uint32_t aoff = base + (wm * 32 + (lane & 15)) * LDAB + (lane >> 4) * 16;
        const uint32_t woff = base + 2 * BUFB + (wn * 64 + (lane & 15)) * LDAB + (lane >> 4) * 16;

#pragma unroll
        for (int ks = 0; ks < 4; ks++) {
            const uint32_t kb2 = ks * 32;
            uint32_t ah[2][4], al[2][4], wh[4][4];
            ldmx4(ah[0], aoff + kb2);
            ldmx4(ah[1], aoff + 16 * LDAB + kb2);
            ldmx4(al[0], aoff + BUFB + kb2);
            ldmx4(al[1], aoff + BUFB + 16 * LDAB + kb2);
#pragma unroll
            for (int p = 0; p < 4; p++)
                ldmx4(wh[p], woff + p * 16 * LDAB + kb2);
#pragma unroll
            for (int mt = 0; mt < 2; mt++)
#pragma unroll
                for (int nt = 0; nt < 8; nt++) {
                    uint32_t b0h = wh[nt >> 1][nt & 1], b1h = wh[nt >> 1][2 + (nt & 1)];
                    mma16816h(c[mt][nt], ah[mt], b0h, b1h);
                    mma16816h(c[mt][nt], al[mt], b0h, b1h);
                }
        }
        __syncthreads();
    }

#pragma unroll
    for (int mt = 0; mt < 2; mt++)
#pragma unroll
        for (int nt = 0; nt < 8; nt++) {
            const int mrow = m0 + wm * 32 + mt * 16 + g;
            const int ncol = n0 + wn * 64 + nt * 8 + t * 2;
            const float b0 = bias[ncol], b1 = bias[ncol + 1];
#pragma unroll
            for (int half = 0; half < 2; half++) {
                const int m = mrow + half * 8;
                float v0 = c[mt][nt][half * 2 + 0] + b0;
                float v1 = c[mt][nt][half * 2 + 1] + b1;
                if (MODE == 0) {
                    v0 = fmaxf(v0, 0.0f); v1 = fmaxf(v1, 0.0f);
                    unsigned int i0 = (unsigned int)(m * 2048 + ncol);
                    unsigned int bt0 = threefry_fold(i0);
                    unsigned int bt1 = threefry_fold(i0 + 1);
                    float u0 = __uint_as_float((bt0 >> 9) | 0x3f800000u) - 1.0f;
                    float u1 = __uint_as_float((bt1 >> 9) | 0x3f800000u) - 1.0f;
                    v0 = (u0 < 0.7f) ? v0 * (1.0f / 0.7f) : 0.0f;
                    v1 = (u1 < 0.7f) ? v1 * (1.0f / 0.7f) : 0.0f;
                    *(float2*)(Cf + (size_t)m * 2048 + ncol) = make_float2(v0, v1);
                    __half h0 = __float2half_rn(v0);
                    __half h1 = __float2half_rn(v1);
                    *(__half2*)(Ch + (size_t)m * 2048 + ncol) = __half2(h0, h1);
                    *(__half2*)(Cl + (size_t)m * 2048 + ncol) = __half2(
                        __float2half_rn(v0 - __half2float(h0)),
                        __float2half_rn(v1 - __half2float(h1)));
                } else {
                    int rp = (m & 63) * 128 + (m >> 6);
                    *(float2*)(Cf + (size_t)rp * Nout + ncol) = make_float2(v0, v1);
                }
            }
        }
}

// ======= persistent GRU scan — 128 threads (R11 structure), fp16 2-pass (W residual dropped) ==
#define PW_PITCH 2064
#define PS_WH 0
#define PS_AH (48 * PW_PITCH)                  // 99072
#define PABUF (64 * LDAB)                      // 9216
#define PS_AL (PS_AH + PABUF)                  // 108288
#define PS_TOTAL (PS_AL + PABUF)               // 117504

__global__ __launch_bounds__(128) void gru_persist(
    const __half* __restrict__ Wp,
    const float* __restrict__ gi, const float* __restrict__ bhh,
    __half* __restrict__ hbh, __half* __restrict__ hbl)
{
    extern __shared__ char smem[];
    const uint32_t sb = smem_u32(smem);
    const int tid = threadIdx.x;
    const int wm = tid >> 5, lane = tid & 31;
    const int nb = blockIdx.x;           // unit block (16 units)
    const int m0 = blockIdx.y * 64;
    const int np0 = nb * 48;

    // ---- preload resident W (fp16 hi only): 6144 x 16B, 48/thread ----
    for (int it = 0; it < 48; it++) {
        int id = tid + it * 128;
        int row = id >> 7, c = id & 127;
        const char* src = (const char*)Wp + (size_t)(np0 + row) * 2048 + c * 16;
        cp_async16(sb + PS_WH + row * PW_PITCH + c * 16, src);
    }
    asm volatile("cp.async.commit_group;" ::: "memory");
    asm volatile("cp.async.wait_group 0;" ::: "memory");
    __syncthreads();

    for (int t = 0; t < NSTEP; t++) {
        const __half* Hh = hbh + (size_t)(t & 1) * NSEQ * HID;
        const __half* Hl = hbl + (size_t)(t & 1) * NSEQ * HID;

        float c[6][4];
#pragma unroll
        for (int j = 0; j < 6; j++)
#pragma unroll
            for (int q = 0; q < 4; q++) c[j][q] = 0.0f;

        uint4 rg[8];
#pragma unroll
        for (int it = 0; it < 8; it++) {
            int id = tid + it * 128;
            int buf = id >> 9, local = id & 511;
            int row = local >> 3, cc = local & 7;
            const char* src = (const char*)(buf ? Hl : Hh)
                              + (size_t)(m0 + row) * 2048 + cc * 16;
            rg[it] = *(const uint4*)src;
        }

#pragma unroll 1
        for (int ch = 0; ch < 16; ch++) {
#pragma unroll
            for (int it = 0; it < 8; it++) {
                int id = tid + it * 128;
                int buf = id >> 9, local = id & 511;
                int row = local >> 3, cc = local & 7;
                *(uint4*)(smem + (buf ? PS_AL : PS_AH) + row * LDAB + cc * 16) = rg[it];
            }
            __syncthreads();
            if (ch < 15) {
#pragma unroll
                for (int it = 0; it < 8; it++) {
                    int id = tid + it * 128;
                    int buf = id >> 9, local = id & 511;
                    int row = local >> 3, cc = local & 7;
                    const char* src = (const char*)(buf ? Hl : Hh)
                                      + (size_t)(m0 + row) * 2048 + (ch + 1) * 128 + cc * 16;
                    rg[it] = *(const uint4*)src;
                }
            }
            const uint32_t aoff  = sb + PS_AH + (wm * 16 + (lane & 15)) * LDAB + (lane >> 4) * 16;
            const uint32_t aoffL = sb + PS_AL + (wm * 16 + (lane & 15)) * LDAB + (lane >> 4) * 16;
            const uint32_t whoff = sb + PS_WH + (lane & 15) * PW_PITCH + (lane >> 4) * 16;
#pragma unroll
            for (int ks = 0; ks < 4; ks++) {
                const uint32_t kbA = ks * 32;
                const uint32_t kbW = (ch * 4 + ks) * 32;
                uint32_t ah[4], al[4], wh[3][4];
                ldmx4(ah, aoff + kbA);
                ldmx4(al, aoffL + kbA);
#pragma unroll
                for (int p = 0; p < 3; p++)
                    ldmx4(wh[p], whoff + p * 16 * PW_PITCH + kbW);
#pragma unroll
                for (int p = 0; p < 3; p++)
#pragma unroll
                    for (int half = 0; half < 2; half++) {
                        float* cc = c[p * 2 + half];
                        mma16816h(cc, ah, wh[p][half], wh[p][2 + half]);
                        mma16816h(cc, al, wh[p][half], wh[p][2 + half]);
                    }
            }
            __syncthreads();
        }

        // ---- fused gate epilogue (mapping validated R9/R11) ----
        const float* hprev = g_hall + (size_t)t * NSEQ * HID;
        float* hout        = g_hall + (size_t)(t + 1) * NSEQ * HID;
        __half* Oh = hbh + (size_t)((t + 1) & 1) * NSEQ * HID;
        __half* Ol = hbl + (size_t)((t + 1) & 1) * NSEQ * HID;
#pragma unroll
        for (int half = 0; half < 2; half++) {
            const int unit0 = nb * 16 + half * 8 + (lane & 3) * 2;
            const float2 br2 = *(const float2*)(bhh + unit0);
            const float2 bz2 = *(const float2*)(bhh + HID + unit0);
            const float2 bn2 = *(const float2*)(bhh + 2 * HID + unit0);
#pragma unroll
            for (int mh = 0; mh < 2; mh++) {
                const int n = m0 + wm * 16 + (lane >> 2) + mh * 8;
                const size_t gib = (size_t)(t * 128 + n) * GI_N;
                const float2 ir2 = *(const float2*)(gi + gib + unit0);
                const float2 iz2 = *(const float2*)(gi + gib + HID + unit0);
                const float2 in2 = *(const float2*)(gi + gib + 2 * HID + unit0);
                const float2 hp2 = *(const float2*)(hprev + (size_t)n * HID + unit0);
                float h2[2];
#pragma unroll
                for (int e = 0; e < 2; e++) {
                    const int ci = mh * 2 + e;
                    float ir = e ? ir2.y : ir2.x, iz = e ? iz2.y : iz2.x, in_ = e ? in2.y : in2.x;
                    float br = e ? br2.y : br2.x, bz = e ? bz2.y : bz2.x, bn = e ? bn2.y : bn2.x;
                    float hp = e ? hp2.y : hp2.x;
                    float r  = sigmoidf_(ir + c[half][ci] + br);
                    float z  = sigmoidf_(iz + c[2 + half][ci] + bz);
                    float nn = tanhf(in_ + r * (c[4 + half][ci] + bn));
                    h2[e] = (1.0f - z) * nn + z * hp;
                }
                *(float2*)(hout + (size_t)n * HID + unit0) = make_float2(h2[0], h2[1]);
                __half b0 = __float2half_rn(h2[0]);
                __half b1 = __float2half_rn(h2[1]);
                *(__half2*)(Oh + (size_t)n * HID + unit0) = __half2(b0, b1);
                *(__half2*)(Ol + (size_t)n * HID + unit0) = __half2(
                    __float2half_rn(h2[0] - __half2float(b0)),
                    __float2half_rn(h2[1] - __half2float(b1)));
            }
        }

        // ---- grid barrier ----
        __syncthreads();
        if (tid == 0) {
            __threadfence();
            atomicAdd(&g_bar, 1u);
            const unsigned int target = 128u * (unsigned int)(t + 1);
            while (*(volatile unsigned int*)&g_bar < target) __nanosleep(64);
        }
        __syncthreads();
    }
}

// ======================= vl & cf small-N GEMMs (unchanged, validated) =========================
__global__ __launch_bounds__(256) void vl_kernel(
    const float* __restrict__ A, const float* __restrict__ W,
    const float* __restrict__ bias, float* __restrict__ out)
{
    __shared__ float As[32][65];
    __shared__ float Ws[24][65];
    const int tid = threadIdx.x;
    const int r = tid >> 3, s = tid & 7;
    const int r0 = blockIdx.x * 32;
    float acc[3] = {0.f, 0.f, 0.f};

    for (int kc = 0; kc < FEAT; kc += 64) {
#pragma unroll
        for (int jj = 0; jj < 2; jj++) {
            int id = tid + jj * 256;
            int row = id >> 4, q = id & 15;
            float4 v = *(const float4*)(A + (size_t)(r0 + row) * FEAT + kc + q * 4);
            As[row][q*4+0] = v.x; As[row][q*4+1] = v.y;
            As[row][q*4+2] = v.z; As[row][q*4+3] = v.w;
        }
#pragma unroll
        for (int jj = 0; jj < 2; jj++) {
            int id = tid + jj * 256;
            if (id < 21 * 16) {
                int row = id >> 4, q = id & 15;
                float4 v = *(const float4*)(W + (size_t)row * FEAT + kc + q * 4);
                Ws[row][q*4+0] = v.x; Ws[row][q*4+1] = v.y;
                Ws[row][q*4+2] = v.z; Ws[row][q*4+3] = v.w;
            }
        }
        __syncthreads();
#pragma unroll
        for (int kk = 0; kk < 64; kk++) {
            float a = As[r][kk];
#pragma unroll
            for (int cc = 0; cc < 3; cc++) {
                int c = s + 8 * cc;
                if (c < NCLS) acc[cc] += a * Ws[c][kk];
            }
        }
        __syncthreads();
    }
    int row = r0 + r;
#pragma unroll
    for (int cc = 0; cc < 3; cc++) {
        int c = s + 8 * cc;
        if (c < NCLS) out[(size_t)row * NCLS + c] = acc[cc] + bias[c];
    }
}

__global__ __launch_bounds__(256) void cf_kernel(
    const float* __restrict__ Hrows,
    const float* __restrict__ cfw, const float* __restrict__ cfb,
    const float* __restrict__ mkw, const float* __restrict__ mkb,
    float* __restrict__ enc, float* __restrict__ mask)
{
    __shared__ float As[32][65];
    __shared__ float Ws[24][65];
    const int tid = threadIdx.x;
    const int r = tid >> 3, s = tid & 7;
    const int r0 = blockIdx.x * 32;
    float acc[3] = {0.f, 0.f, 0.f};

    for (int kc = 0; kc < HID; kc += 64) {
#pragma unroll
        for (int jj = 0; jj < 2; jj++) {
            int id = tid + jj * 256;
            int row = id >> 4, q = id & 15;
            float4 v = *(const float4*)(Hrows + (size_t)(r0 + row) * HID + kc + q * 4);
            As[row][q*4+0] = fmaxf(v.x, 0.0f); As[row][q*4+1] = fmaxf(v.y, 0.0f);
            As[row][q*4+2] = fmaxf(v.z, 0.0f); As[row][q*4+3] = fmaxf(v.w, 0.0f);
        }
#pragma unroll
        for (int jj = 0; jj < 2; jj++) {
            int id = tid + jj * 256;
            if (id < 24 * 16) {
                int row = id >> 4, q = id & 15;
                const float* src = (row < 22) ? (cfw + (size_t)row * HID)
                                              : (mkw + (size_t)(row - 22) * HID);
                float4 v = *(const float4*)(src + kc + q * 4);
                Ws[row][q*4+0] = v.x; Ws[row][q*4+1] = v.y;
                Ws[row][q*4+2] = v.z; Ws[row][q*4+3] = v.w;
            }
        }
        __syncthreads();
#pragma unroll
        for (int kk = 0; kk < 64; kk++) {
            float a = As[r][kk];
#pragma unroll
            for (int cc = 0; cc < 3; cc++) {
                int c = s + 8 * cc;
                acc[cc] += a * Ws[c][kk];
            }
        }
        __syncthreads();
    }
    int row = r0 + r;
#pragma unroll
    for (int cc = 0; cc < 3; cc++) {
        int c = s + 8 * cc;
        float b = (c < 22) ? cfb[c] : mkb[c - 22];
        float val = acc[cc] + b;
        if (c < 22) enc[(size_t)row * 22 + c] = val;
        else        mask[(size_t)row * 2 + (c - 22)] = val;
    }
}

// ======================= launch (sequential topology) =========================================
extern "C" void kernel_launch(void* const* d_in, const int* in_sizes, int n_in,
                              void* d_out, int out_size)
{
    const float* feats = (const float*)d_in[0];
    const float* fc_w  = (const float*)d_in[1];
    const float* fc_b  = (const float*)d_in[2];
    const float* cls_w = (const float*)d_in[3];
    const float* cls_b = (const float*)d_in[4];
    const float* w_ih  = (const float*)d_in[5];
    const float* w_hh  = (const float*)d_in[6];
    const float* b_ih  = (const float*)d_in[7];
    const float* b_hh  = (const float*)d_in[8];
    const float* cf_w  = (const float*)d_in[9];
    const float* cf_b  = (const float*)d_in[10];
    const float* mk_w  = (const float*)d_in[11];
    const float* mk_b  = (const float*)d_in[12];

    float* out  = (float*)d_out;
    float* enc  = out;
    float* mask = out + 8192 * 22;
    float* xbuf = out + 8192 * 22 + 8192 * 2;
    float* vl   = xbuf + (size_t)ROWS * FEAT;

    float *gi_ptr, *hall_ptr;
    __half *fh, *fl, *xh, *xl, *wfh, *wfl, *wihh, *wihl, *whp, *hbh, *hbl;
    unsigned int* bar_ptr;
    cudaGetSymbolAddress((void**)&gi_ptr, g_gi);
    cudaGetSymbolAddress((void**)&hall_ptr, g_hall);
    cudaGetSymbolAddress((void**)&fh, g_fh);   cudaGetSymbolAddress((void**)&fl, g_fl);
    cudaGetSymbolAddress((void**)&xh, g_xh);   cudaGetSymbolAddress((void**)&xl, g_xl);
    cudaGetSymbolAddress((void**)&wfh, g_wfh); cudaGetSymbolAddress((void**)&wfl, g_wfl);
    cudaGetSymbolAddress((void**)&wihh, g_wih); cudaGetSymbolAddress((void**)&wihl, g_wil);
    cudaGetSymbolAddress((void**)&whp, g_whp);
    cudaGetSymbolAddress((void**)&hbh, g_hbh); cudaGetSymbolAddress((void**)&hbl, g_hbl);
    cudaGetSymbolAddress((void**)&bar_ptr, g_bar);

    cudaFuncSetAttribute(mma_gemm<0>, cudaFuncAttributeMaxDynamicSharedMemorySize, MM_SMEM);
    cudaFuncSetAttribute(mma_gemm<1>, cudaFuncAttributeMaxDynamicSharedMemorySize, MM_SMEM);
    cudaFuncSetAttribute(gru_persist, cudaFuncAttributeMaxDynamicSharedMemorySize, PS_TOTAL);

    // 0. converts + resets
    convert_hilo_h<<<(ROWS * FEAT) / 1024, 256>>>(feats, fh, fl, ROWS * FEAT);
    convert_hilo_h<<<(FEAT * FEAT) / 1024, 256>>>(fc_w, wfh, wfl, FEAT * FEAT);
    convert_hilo_h<<<(GI_N * FEAT) / 1024, 256>>>(w_ih, wihh, wihl, GI_N * FEAT);
    convert_whh_perm<<<(GI_N * HID) / 1024, 256>>>(w_hh, whp);
    cudaMemsetAsync(bar_ptr, 0, sizeof(unsigned int));
    cudaMemsetAsync(hall_ptr, 0, (size_t)NSEQ * HID * sizeof(float));
    cudaMemsetAsync(hbh, 0, (size_t)NSEQ * HID * sizeof(__half));
    cudaMemsetAsync(hbl, 0, (size_t)NSEQ * HID * sizeof(__half));

    // 1. fc GEMM (fp16 2-pass) + fused epilogue
    mma_gemm<0><<<dim3(FEAT / 128, ROWS / 128), 256, MM_SMEM>>>(
        fh, fl, wfh, fc_b, xbuf, xh, xl, FEAT, FEAT);

    // 2. vl_preds
    vl_kernel<<<ROWS / 32, 256>>>(xbuf, cls_w, cls_b, vl);

    // 3. gi (fp16 2-pass, time-major)
    mma_gemm<1><<<dim3(GI_N / 128, ROWS / 128), 256, MM_SMEM>>>(
        xh, xl, wihh, b_ih, gi_ptr, nullptr, nullptr, FEAT, GI_N);

    // 4. persistent GRU scan (fp16 2-pass, W resident in smem)
    gru_persist<<<dim3(64, 2), 128, PS_TOTAL>>>(whp, gi_ptr, b_hh, hbh, hbl);

    // 5. enc/mask scores
    cf_kernel<<<ROWS / 32, 256>>>(hall_ptr + (size_t)NSEQ * HID,
                                  cf_w, cf_b, mk_w, mk_b, enc, mask);
}